// round 1
// baseline (speedup 1.0000x reference)
#include <cuda_runtime.h>

#define EPSF 1e-8f

// Affine-scan solver for the reverse linear recurrence
//   v_t = gamma*(1 - l_t) + gamma*l_t * v_{t+1},  v_T = 1
//   w_t = max(1 - v_t, eps);  out = w / max(mean(w), eps)
// T = 4096, lambd[t] = max(tanh(raw_lambd[2048 + (t & 2047)]), eps)
// One block, 128 threads, 32 steps/thread. Processing order u = T-1-t
// (u ascending == reverse-time scan). Each thread composes its 32 affine
// steps into v_out = A + B*v_in, a Hillis-Steele scan over the 128 segment
// maps gives each segment its exact input v, then each thread replays its
// 32 steps sequentially, accumulates the sum, and the block normalizes.
__global__ __launch_bounds__(128, 1)
void gamma_lambda_kernel(const float* __restrict__ raw_gamma,
                         const float* __restrict__ raw_lambd,
                         float* __restrict__ out) {
    constexpr int T   = 4096;
    constexpr int NT  = 128;
    constexpr int SEG = T / NT;  // 32

    __shared__ float shA[NT];
    __shared__ float shB[NT];
    __shared__ float sh_w[T];
    __shared__ float sh_red[NT / 32];
    __shared__ float sh_scale;

    const int tid = threadIdx.x;
    const float gamma = fmaxf(tanhf(raw_gamma[0]), EPSF);

    // Load + transform this thread's 32 lambdas (processing order u ascending).
    float l[SEG];
    const int u0 = tid * SEG;
#pragma unroll
    for (int j = 0; j < SEG; ++j) {
        const int t   = (T - 1) - (u0 + j);
        const int idx = 2048 + (t & 2047);
        l[j] = fmaxf(tanhf(raw_lambd[idx]), EPSF);
    }

    // Compose segment: v_out = A + B * v_in (identity = (0, 1)).
    // One step: v' = a + b*v with b = gamma*l, a = gamma - b.
    float A = 0.0f, B = 1.0f;
#pragma unroll
    for (int j = 0; j < SEG; ++j) {
        const float b = gamma * l[j];
        const float a = gamma - b;
        A = fmaf(b, A, a);
        B = b * B;
    }
    shA[tid] = A;
    shB[tid] = B;
    __syncthreads();

    // Inclusive Hillis-Steele scan of affine maps across the 128 segments.
    // g_k = f_k ∘ g_{k-d}:  A' = A + B*pA,  B' = B*pB.
    float myA = A, myB = B;
#pragma unroll
    for (int d = 1; d < NT; d <<= 1) {
        float pA = 0.0f, pB = 1.0f;
        if (tid >= d) { pA = shA[tid - d]; pB = shB[tid - d]; }
        __syncthreads();
        myA = fmaf(myB, pA, myA);
        myB = myB * pB;
        shA[tid] = myA;
        shB[tid] = myB;
        __syncthreads();
    }

    // v at the input of this segment = prefix map applied to v_T = 1.
    float v = 1.0f;
    if (tid > 0) v = shA[tid - 1] + shB[tid - 1];

    // Replay the segment exactly, produce w, accumulate local sum.
    float lsum = 0.0f;
#pragma unroll
    for (int j = 0; j < SEG; ++j) {
        const float b = gamma * l[j];
        v = fmaf(b, v, gamma - b);
        const float w = fmaxf(1.0f - v, EPSF);
        const int t = (T - 1) - (u0 + j);
        sh_w[t] = w;
        lsum += w;
    }

    // Block reduction of the sum (4 warps).
#pragma unroll
    for (int off = 16; off > 0; off >>= 1)
        lsum += __shfl_xor_sync(0xffffffffu, lsum, off);
    const int wid = tid >> 5, lid = tid & 31;
    if (lid == 0) sh_red[wid] = lsum;
    __syncthreads();
    if (tid == 0) {
        const float total = sh_red[0] + sh_red[1] + sh_red[2] + sh_red[3];
        const float mean  = total * (1.0f / (float)T);
        sh_scale = 1.0f / fmaxf(mean, EPSF);
    }
    __syncthreads();

    // Normalized, coalesced store.
    const float s = sh_scale;
#pragma unroll
    for (int j = 0; j < SEG; ++j) {
        const int t = tid + j * NT;
        out[t] = sh_w[t] * s;
    }
}

extern "C" void kernel_launch(void* const* d_in, const int* in_sizes, int n_in,
                              void* d_out, int out_size) {
    const float* raw_gamma = (const float*)d_in[0];  // scalar
    const float* raw_lambd = (const float*)d_in[1];  // 4096 floats
    float* out = (float*)d_out;                      // 4096 floats (1,4096,1)
    gamma_lambda_kernel<<<1, 128>>>(raw_gamma, raw_lambd, out);
}

// round 2
// speedup vs baseline: 1.2620x; 1.2620x over previous
#include <cuda_runtime.h>

#define EPSF 1e-8f

// Fast, accurate tanh for moderate x: 1 - 2/(exp(2x)+1).
// __expf -> MUFU.EX2 path, ~1e-7 rel err on [0.5, 3]; far inside 1e-3 gate.
__device__ __forceinline__ float tanh_fast(float x) {
    float e = __expf(2.0f * x);
    return 1.0f - __fdividef(2.0f, e + 1.0f);
}

// Reverse linear recurrence v_t = gamma*(1-l_t) + gamma*l_t*v_{t+1}, v_T=1,
// w_t = max(1-v_t, eps), out = w / max(mean(w), eps),  T = 4096.
// lambd[t] = max(tanh(raw_lambd[2048 + (t & 2047)]), eps): only 2048 distinct
// tanh evaluations (both concat halves read the same slice) -> computed once
// into shared. 256 threads x 16 steps; affine-map segment compose + warp
// shuffle scan + 8-aggregate scan; w kept in registers, reversed float4 store.
__global__ __launch_bounds__(256, 1)
void gamma_lambda_kernel(const float* __restrict__ raw_gamma,
                         const float* __restrict__ raw_lambd,
                         float* __restrict__ out) {
    constexpr int T   = 4096;
    constexpr int NT  = 256;
    constexpr int SEG = T / NT;          // 16
    constexpr unsigned FULL = 0xffffffffu;

    __shared__ float sh_l[2048];
    __shared__ float shWA[NT / 32];      // warp aggregate A
    __shared__ float shWB[NT / 32];      // warp aggregate B
    __shared__ float shS[NT / 32];       // warp partial sums
    __shared__ float sh_scale;

    const int tid  = threadIdx.x;
    const int lane = tid & 31;
    const int wid  = tid >> 5;

    const float gamma = fmaxf(tanh_fast(raw_gamma[0]), EPSF);

    // 2048 distinct lambdas (slice raw_lambd[2048:4096]), tanh'd once.
    #pragma unroll
    for (int k = 0; k < 2048 / NT; ++k) {
        const int i = tid + k * NT;
        sh_l[i] = fmaxf(tanh_fast(raw_lambd[2048 + i]), EPSF);
    }
    __syncthreads();

    // Processing order u ascending == reverse time; t = T-1-u.
    // Thread's lambda indices: i = (T-1 - (u0+j)) & 2047.
    const int u0 = tid * SEG;
    float b[SEG];
    #pragma unroll
    for (int j = 0; j < SEG; ++j) {
        const int i = (T - 1 - (u0 + j)) & 2047;
        b[j] = gamma * sh_l[i];          // per-step multiplier; a = gamma - b
    }

    // Compose segment map: v_out = A + B*v_in (identity (0,1)).
    float A = 0.0f, B = 1.0f;
    #pragma unroll
    for (int j = 0; j < SEG; ++j) {
        A = fmaf(b[j], A, gamma - b[j]);
        B = b[j] * B;
    }

    // Inclusive warp scan of affine maps (compose with earlier segments).
    float iA = A, iB = B;
    #pragma unroll
    for (int off = 1; off < 32; off <<= 1) {
        const float pA = __shfl_up_sync(FULL, iA, off);
        const float pB = __shfl_up_sync(FULL, iB, off);
        if (lane >= off) { iA = fmaf(iB, pA, iA); iB *= pB; }
    }
    if (lane == 31) { shWA[wid] = iA; shWB[wid] = iB; }
    __syncthreads();

    // Warp 0 scans the 8 warp aggregates.
    if (wid == 0) {
        float wA = (lane < 8) ? shWA[lane] : 0.0f;
        float wB = (lane < 8) ? shWB[lane] : 1.0f;
        #pragma unroll
        for (int off = 1; off < 8; off <<= 1) {
            const float pA = __shfl_up_sync(FULL, wA, off);
            const float pB = __shfl_up_sync(FULL, wB, off);
            if (lane >= off) { wA = fmaf(wB, pA, wA); wB *= pB; }
        }
        if (lane < 8) { shWA[lane] = wA; shWB[lane] = wB; }
    }
    __syncthreads();

    // Block-exclusive prefix for this thread:
    // within-warp exclusive composed after the preceding-warps prefix.
    float eA = __shfl_up_sync(FULL, iA, 1);
    float eB = __shfl_up_sync(FULL, iB, 1);
    if (lane == 0) { eA = 0.0f; eB = 1.0f; }
    float qA = 0.0f, qB = 1.0f;
    if (wid > 0) { qA = shWA[wid - 1]; qB = shWB[wid - 1]; }
    const float totA = fmaf(eB, qA, eA);
    const float totB = eB * qB;

    // v entering this segment: prefix map applied to v_T = 1.
    float v = totA + totB;

    // Replay segment exactly; keep w in registers; accumulate local sum.
    float w[SEG];
    float lsum = 0.0f;
    #pragma unroll
    for (int j = 0; j < SEG; ++j) {
        v = fmaf(b[j], v, gamma - b[j]);
        w[j] = fmaxf(1.0f - v, EPSF);
        lsum += w[j];
    }

    // Block sum -> normalization scale.
    #pragma unroll
    for (int off = 16; off > 0; off >>= 1)
        lsum += __shfl_xor_sync(FULL, lsum, off);
    if (lane == 0) shS[wid] = lsum;
    __syncthreads();
    if (tid == 0) {
        float total = 0.0f;
        #pragma unroll
        for (int k = 0; k < NT / 32; ++k) total += shS[k];
        const float mean = total * (1.0f / (float)T);
        sh_scale = __fdividef(1.0f, fmaxf(mean, EPSF));
    }
    __syncthreads();

    // Store: thread owns t in [base, base+15], base = T - SEG*(tid+1),
    // with w[j] at t = T-1-u0-j  ->  out[base+k] = w[SEG-1-k]*s.  float4 x4.
    const float s = sh_scale;
    const int base = T - SEG * (tid + 1);
    #pragma unroll
    for (int q = 0; q < SEG / 4; ++q) {
        float4 o;
        o.x = w[SEG - 1 - (4 * q + 0)] * s;
        o.y = w[SEG - 1 - (4 * q + 1)] * s;
        o.z = w[SEG - 1 - (4 * q + 2)] * s;
        o.w = w[SEG - 1 - (4 * q + 3)] * s;
        *reinterpret_cast<float4*>(out + base + 4 * q) = o;
    }
}

extern "C" void kernel_launch(void* const* d_in, const int* in_sizes, int n_in,
                              void* d_out, int out_size) {
    const float* raw_gamma = (const float*)d_in[0];  // scalar
    const float* raw_lambd = (const float*)d_in[1];  // 4096 floats
    float* out = (float*)d_out;                      // 4096 floats (1,4096,1)
    gamma_lambda_kernel<<<1, 256>>>(raw_gamma, raw_lambd, out);
}

// round 3
// speedup vs baseline: 1.5907x; 1.2605x over previous
#include <cuda_runtime.h>

#define EPSF 1e-8f

// Fast, accurate tanh for moderate x>0: 1 - 2/(exp(2x)+1).
// __expf/__fdividef -> MUFU.EX2 + MUFU.RCP; ~1e-7 rel err on [0.5, 3].
__device__ __forceinline__ float tanh_fast(float x) {
    float e = __expf(2.0f * x);
    return 1.0f - __fdividef(2.0f, e + 1.0f);
}

// Reverse linear recurrence v_t = gamma*(1-l_t) + gamma*l_t*v_{t+1}, v_T=1,
// w_t = max(1-v_t, eps), out = w / max(mean(w), eps), T = 4096.
// lambd[t] = max(tanh(raw_lambd[2048 + (t & 2047)]), eps).
// 256 threads x 16 steps, processing order u = T-1-t ascending (reverse time).
// Direct per-thread loads (reversed float4), tanh in regs, affine segment
// compose, warp-shuffle scan + 8-aggregate scan (3 barriers total), replay,
// block sum, reversed float4 store. Entirely latency-bound; minimize phases.
__global__ __launch_bounds__(256, 1)
void gamma_lambda_kernel(const float* __restrict__ raw_gamma,
                         const float* __restrict__ raw_lambd,
                         float* __restrict__ out) {
    constexpr int T   = 4096;
    constexpr int NT  = 256;
    constexpr int SEG = T / NT;          // 16
    constexpr unsigned FULL = 0xffffffffu;

    __shared__ float shWA[NT / 32];
    __shared__ float shWB[NT / 32];
    __shared__ float shS[NT / 32];

    const int tid  = threadIdx.x;
    const int lane = tid & 31;
    const int wid  = tid >> 5;

    // Issue all global loads first so their latency overlaps the tanh work.
    const float rg = __ldg(raw_gamma);
    // Thread's lambda index for step j: idx_j = base - j, with
    // base = 2048 + 2047 - ((u0 + j) mod 2048)|_{j=0} = 4095 - (u0 & 2047).
    // Range stays within [2048, 4095]; base-15 is 16B-aligned.
    const int u0   = tid * SEG;
    const int base = 4095 - (u0 & 2047);
    float l[SEG];
#pragma unroll
    for (int q = 0; q < SEG / 4; ++q) {
        const float4 v4 =
            *reinterpret_cast<const float4*>(raw_lambd + base - 4 * q - 3);
        l[4 * q + 0] = v4.w;
        l[4 * q + 1] = v4.z;
        l[4 * q + 2] = v4.y;
        l[4 * q + 3] = v4.x;
    }

    const float gamma = fmaxf(tanh_fast(rg), EPSF);

    // Per-step multiplier b = gamma * lambda (a = gamma - b).
    float b[SEG];
#pragma unroll
    for (int j = 0; j < SEG; ++j)
        b[j] = gamma * fmaxf(tanh_fast(l[j]), EPSF);

    // Compose segment map: v_out = A + B*v_in (identity (0,1)).
    float A = 0.0f, B = 1.0f;
#pragma unroll
    for (int j = 0; j < SEG; ++j) {
        A = fmaf(b[j], A, gamma - b[j]);
        B = b[j] * B;
    }

    // Inclusive warp scan of affine maps.
    float iA = A, iB = B;
#pragma unroll
    for (int off = 1; off < 32; off <<= 1) {
        const float pA = __shfl_up_sync(FULL, iA, off);
        const float pB = __shfl_up_sync(FULL, iB, off);
        if (lane >= off) { iA = fmaf(iB, pA, iA); iB *= pB; }
    }
    if (lane == 31) { shWA[wid] = iA; shWB[wid] = iB; }
    __syncthreads();                                    // barrier 1

    // Warp 0 scans the 8 warp aggregates.
    if (wid == 0) {
        float wA = (lane < NT / 32) ? shWA[lane] : 0.0f;
        float wB = (lane < NT / 32) ? shWB[lane] : 1.0f;
#pragma unroll
        for (int off = 1; off < NT / 32; off <<= 1) {
            const float pA = __shfl_up_sync(FULL, wA, off);
            const float pB = __shfl_up_sync(FULL, wB, off);
            if (lane >= off) { wA = fmaf(wB, pA, wA); wB *= pB; }
        }
        if (lane < NT / 32) { shWA[lane] = wA; shWB[lane] = wB; }
    }
    __syncthreads();                                    // barrier 2

    // Block-exclusive prefix: within-warp exclusive after prior-warp prefix.
    float eA = __shfl_up_sync(FULL, iA, 1);
    float eB = __shfl_up_sync(FULL, iB, 1);
    if (lane == 0) { eA = 0.0f; eB = 1.0f; }
    float qA = 0.0f, qB = 1.0f;
    if (wid > 0) { qA = shWA[wid - 1]; qB = shWB[wid - 1]; }
    const float totA = fmaf(eB, qA, eA);
    const float totB = eB * qB;

    // v entering this segment: prefix map applied to v_T = 1.
    float v = totA + totB;

    // Replay segment exactly; keep w in registers; accumulate local sum.
    float w[SEG];
    float lsum = 0.0f;
#pragma unroll
    for (int j = 0; j < SEG; ++j) {
        v = fmaf(b[j], v, gamma - b[j]);
        w[j] = fmaxf(1.0f - v, EPSF);
        lsum += w[j];
    }

    // Block sum: warp reduce, then every thread sums the 8 partials itself
    // (no broadcast barrier needed).
#pragma unroll
    for (int off = 16; off > 0; off >>= 1)
        lsum += __shfl_xor_sync(FULL, lsum, off);
    if (lane == 0) shS[wid] = lsum;
    __syncthreads();                                    // barrier 3

    float total = 0.0f;
#pragma unroll
    for (int k = 0; k < NT / 32; ++k) total += shS[k];
    const float mean = total * (1.0f / (float)T);
    const float s = __fdividef(1.0f, fmaxf(mean, EPSF));

    // Store: thread owns t in [obase, obase+15], obase = T - SEG*(tid+1);
    // w[j] lives at t = T-1-u0-j -> out[obase+k] = w[SEG-1-k]*s.
    const int obase = T - SEG * (tid + 1);
#pragma unroll
    for (int q = 0; q < SEG / 4; ++q) {
        float4 o;
        o.x = w[SEG - 1 - (4 * q + 0)] * s;
        o.y = w[SEG - 1 - (4 * q + 1)] * s;
        o.z = w[SEG - 1 - (4 * q + 2)] * s;
        o.w = w[SEG - 1 - (4 * q + 3)] * s;
        *reinterpret_cast<float4*>(out + obase + 4 * q) = o;
    }
}

extern "C" void kernel_launch(void* const* d_in, const int* in_sizes, int n_in,
                              void* d_out, int out_size) {
    const float* raw_gamma = (const float*)d_in[0];  // scalar
    const float* raw_lambd = (const float*)d_in[1];  // 4096 floats
    float* out = (float*)d_out;                      // 4096 floats (1,4096,1)
    gamma_lambda_kernel<<<1, 256>>>(raw_gamma, raw_lambd, out);
}